// round 15
// baseline (speedup 1.0000x reference)
#include <cuda_runtime.h>
#include <stdint.h>

#define RNODES 256
#define LUT_LEN 262144            // 2^18 entries per node
#define NSTEP 512
#define NSAMP 512
#define NIN 32
#define NOUT 10

// LUT window: 131072 values = 4096 words = 16 KB per node.
// lo_t = max(0, rowsum_t+1-131072) ceil-aligned to 32 -> provably covers
// [lo_t, rowsum_t] (and [0, rowsum_t] entirely when rowsum_t < 131072,
// which holds for essentially every node).
#define WIN_VALS 131072
#define WIN_WORDS 4096

// 6-bit half-groups: 43 (last covers k=252..255; k>=256 guarded to zero)
#define NH6 43
#define TAB6_ROWS (NH6 * 64)
// 12-bit groups: 21 full (g=0..20, k=0..251) + one 4-bit tail (k=252..255)
#define NG12 21
#define TAB12_TAIL (NG12 * 4096)        // 86016
#define TAB12_ROWS (TAB12_TAIL + 16)    // 86032 rows x 128 u32-pairs = 44 MB

// Static device scratch (allocation-free rule).
__device__ uint32_t g_win4[RNODES * WIN_WORDS];      // 4 MB windowed LUT bits
__device__ uint32_t g_lo[RNODES];                    // per-node window base
__device__ uint16_t g_tab6[TAB6_ROWS * RNODES];      // 1.4 MB half tables
__device__ uint32_t g_tab12[TAB12_ROWS * 128];       // 44 MB pair table (L2)
__device__ uint32_t g_xpack[NSAMP * NSTEP];          // per (m,s): 32 input bits
__device__ int      g_inv[RNODES];                   // node -> input slot, or -1
__device__ int      g_init[RNODES];                  // initial state bits
__device__ int      g_mode;                          // bool enc: 0=i32 1=u8 2=f32

__device__ __forceinline__ int read_bool(const void* p, long i, int mode) {
    if (mode == 0) return ((const int*)p)[i] != 0;
    if (mode == 1) return ((const unsigned char*)p)[i] != 0;
    return ((const float*)p)[i] != 0.0f;
}

__global__ void detect_kernel(const uint32_t* __restrict__ xw) {
    int lane = threadIdx.x;
    if (blockIdx.x || lane >= 32) return;
    int isf = 0, big = 0;
    for (int i = 0; i < 32; i++) {
        uint32_t v = xw[i * 32 + lane];
        if (v == 0x3f800000u) isf = 1;
        if (v > 1u) big = 1;
    }
    unsigned af = __ballot_sync(0xffffffffu, isf);
    unsigned ab = __ballot_sync(0xffffffffu, big);
    if (lane == 0) g_mode = af ? 2 : (ab ? 1 : 0);
}

// Per-node window base from the EXACT reachable bound: idx <= rowsum_t.
// lo_t = max(0, rowsum+1-131072), ceil-aligned to 32 so lo+WIN_VALS > rowsum.
// Also inv/init. One thread per node.
__global__ void center_kernel(const void* __restrict__ W,
                              const int* __restrict__ primes,
                              const int* __restrict__ input_nodes,
                              const void* __restrict__ init_res) {
    int t = blockIdx.x * blockDim.x + threadIdx.x;
    if (t >= RNODES) return;
    int mode = g_mode;
    long row = (long)t * RNODES;
    uint32_t rowsum = 0;
    for (int k = 0; k < RNODES; k++)
        if (read_bool(W, row + k, mode)) rowsum += (uint32_t)primes[k];
    int lo = (int)rowsum + 1 - WIN_VALS;
    if (lo < 0) lo = 0;
    lo = (lo + 31) & ~31;                     // ceil-align keeps top coverage
    if (lo > LUT_LEN - WIN_VALS) lo = LUT_LEN - WIN_VALS;
    g_lo[t] = (uint32_t)lo;

    int inv = -1;
#pragma unroll
    for (int q = 0; q < NIN; q++)
        if (input_nodes[q] == t) inv = q;
    g_inv[t] = inv;
    g_init[t] = read_bool(init_res, t, mode);
}

// Pack the 128 MB of windowed LUT columns (warp-ballot, fully coalesced).
// 32768 warps: warp gw -> node gw/128, chunk gw%128 (32 words = 1024 values).
__global__ void pack_win_kernel(const int* __restrict__ lut) {
    int gw   = (blockIdx.x * blockDim.x + threadIdx.x) >> 5;
    int lane = threadIdx.x & 31;
    if (gw >= RNODES * 128) return;
    int node = gw >> 7, chunk = gw & 127;
    const int* src = lut + (size_t)node * LUT_LEN + g_lo[node] + chunk * 1024;
    uint32_t mine = 0;
#pragma unroll
    for (int w = 0; w < 32; w++) {
        int v = src[w * 32 + lane];
        unsigned m = __ballot_sync(0xffffffffu, v & 1);
        if (lane == w) mine = m;
    }
    g_win4[node * WIN_WORDS + chunk * 32 + lane] = mine;
}

// Warp-ballot x pack: 262144 words / 32 per warp = 8192 warps.
__global__ void pack_x_kernel(const void* __restrict__ x) {
    int gwarp = (blockIdx.x * blockDim.x + threadIdx.x) >> 5;
    int lane  = threadIdx.x & 31;
    int mode  = g_mode;
    long base = (long)gwarp * 1024;
    uint32_t mine = 0;
#pragma unroll
    for (int w = 0; w < 32; w++) {
        int v = read_bool(x, base + w * 32 + lane, mode);
        unsigned m = __ballot_sync(0xffffffffu, v);
        if (lane == w) mine = m;
    }
    g_xpack[gwarp * 32 + lane] = mine;
}

// 6-bit half tables
#define SEC_T6 (TAB6_ROWS * RNODES)
__global__ void prep_tab6_kernel(const void* __restrict__ W,
                                 const int* __restrict__ primes) {
    int i = blockIdx.x * blockDim.x + threadIdx.x;
    if (i >= SEC_T6) return;
    int mode = g_mode;
    int node = i & 255;
    int c    = (i >> 8) & 63;
    int h    = i >> 14;
    uint32_t sum = 0;
#pragma unroll
    for (int j = 0; j < 6; j++) {
        int k = 6 * h + j;
        if ((c & (1 << j)) && k < RNODES) {
            if (read_bool(W, (long)node * RNODES + k, mode))
                sum += (uint32_t)primes[k];
        }
    }
    g_tab6[i] = (uint16_t)sum;
}

// Build paired 12-bit table from 6-bit halves (write-bound, 44 MB).
// Entry (row, t): u16 pair {node t, node t+128}.
__global__ void prep2_kernel() {
    int i = blockIdx.x * blockDim.x + threadIdx.x;
    if (i >= TAB12_ROWS * 128) return;
    int t   = i & 127;
    int row = i >> 7;
    uint32_t lo, hi;
    if (row < TAB12_TAIL) {
        int g  = row >> 12;
        int c  = row & 4095;
        int r0 = (2 * g) * 64 + (c & 63);
        int r1 = (2 * g + 1) * 64 + (c >> 6);
        lo = (uint32_t)g_tab6[r0 * RNODES + t]
           + (uint32_t)g_tab6[r1 * RNODES + t];
        hi = (uint32_t)g_tab6[r0 * RNODES + t + 128]
           + (uint32_t)g_tab6[r1 * RNODES + t + 128];
    } else {
        int r = 42 * 64 + (row - TAB12_TAIL);     // k = 252..255
        lo = g_tab6[r * RNODES + t];
        hi = g_tab6[r * RNODES + t + 128];
    }
    g_tab12[i] = lo | (hi << 16);
}

// 512 CTAs x 128 threads. CTA = one sample; thread t owns nodes t and t+128.
// EXACT R8 hot kernel; the only changes vs R8: accumulators start at -lo_t
// (folding the window rebase into the existing adds) and the gather indexes
// the 4 MB window with t<<12 instead of the 8 MB full pack with t<<13.
// No compares, no selects, no fallback: coverage is guaranteed by prep.
__global__ void __launch_bounds__(128, 4)
reservoir_kernel(const float* __restrict__ roW,
                 const float* __restrict__ rob,
                 float* __restrict__ out) {
    __shared__ uint32_t sh_xw[NSTEP];
    __shared__ uint32_t sh_r[16];       // 2 bufs * 8 mask words
    __shared__ float    sh_bits[RNODES];

    const int t    = threadIdx.x;       // 0..127
    const int w    = t >> 5;
    const int lane = t & 31;
    const int sid  = blockIdx.x;

    for (int i = t; i < NSTEP; i += 128)
        sh_xw[i] = g_xpack[sid * NSTEP + i];

    const int inv0 = g_inv[t];
    const int inv1 = g_inv[t + 128];
    const uint32_t nlo0 = (uint32_t)(-(int)g_lo[t]);
    const uint32_t nlo1 = (uint32_t)(-(int)g_lo[t + 128]);
    unsigned b0 = (unsigned)g_init[t];
    unsigned b1 = (unsigned)g_init[t + 128];

    __syncthreads();

    for (int s = 0; s < NSTEP; s++) {
        // 1) input override (before the matvec, as in the reference)
        uint32_t xw = sh_xw[s];
        unsigned a0 = (inv0 >= 0) ? ((xw >> inv0) & 1u) : b0;
        unsigned a1 = (inv1 >= 0) ? ((xw >> inv1) & 1u) : b1;

        // 2) state bitmask words: warp w -> words w and w+4
        unsigned m0 = __ballot_sync(0xffffffffu, a0);
        unsigned m1 = __ballot_sync(0xffffffffu, a1);
        uint32_t* rb = sh_r + (s & 1) * 8;
        if (lane == 0) { rb[w] = m0; rb[w + 4] = m1; }
        __syncthreads();

        uint4 ra  = *(const uint4*)(rb);
        uint4 rb4 = *(const uint4*)(rb + 4);
        uint32_t wv[8] = {ra.x, ra.y, ra.z, ra.w, rb4.x, rb4.y, rb4.z, rb4.w};

        // 3) 12-bit-group pair sums: 22 independent coalesced LDG.32.
        //    Accumulators start at -lo so the final value IS the window offset.
        uint32_t i0 = nlo0, i1 = nlo1;
#pragma unroll
        for (int trip = 0; trip < 7; trip++) {
            uint32_t acc = 0;   // packed u16; 3 groups max < 58.3K
#pragma unroll
            for (int j = 0; j < 3; j++) {
                int g  = trip * 3 + j;
                int bp = 12 * g;
                int wi = bp >> 5, sh = bp & 31;
                uint32_t c = __funnelshift_r(wv[wi], wv[(wi + 1) & 7], sh) & 0xFFFu;
                acc = __vadd2(acc, g_tab12[((uint32_t)g << 19) + (c << 7) + t]);
            }
            i0 += acc & 0xFFFFu;
            i1 += acc >> 16;
        }
        {   // tail 4-bit group (nodes k=252..255)
            uint32_t c = wv[7] >> 28;
            uint32_t e = g_tab12[((uint32_t)TAB12_TAIL << 7) + (c << 7) + t];
            i0 += e & 0xFFFFu;
            i1 += e >> 16;
        }

        // 4) windowed LUT gather (4 MB, L2-resident), unconditional
        uint32_t w0 = g_win4[((uint32_t)t << 12)         + (i0 >> 5)];
        uint32_t w1 = g_win4[((uint32_t)(t + 128) << 12) + (i1 >> 5)];
        b0 = (w0 >> (i0 & 31u)) & 1u;
        b1 = (w1 >> (i1 & 31u)) & 1u;
    }

    // Readout: out[m, o] = sum_j rf[m,j] * roW[o,j] + rob[o]
    sh_bits[t]       = (float)b0;
    sh_bits[t + 128] = (float)b1;
    __syncthreads();

    if (t < NOUT) {
        float acc = rob[t];
        const float* wrow = roW + t * RNODES;
#pragma unroll 8
        for (int j = 0; j < RNODES; j++)
            acc += sh_bits[j] * wrow[j];
        out[sid * NOUT + t] = acc;
    }
}

extern "C" void kernel_launch(void* const* d_in, const int* in_sizes, int n_in,
                              void* d_out, int out_size) {
    const void* x       = d_in[0];                   // bool [512,512,4,8] (dtype-detected)
    const int*  innod   = (const int*)d_in[1];       // int32 [32]
    const int*  lut     = (const int*)d_in[2];       // int32 [256, 262144]
    const void* W       = d_in[3];                   // bool [256,256]
    const int*  primes  = (const int*)d_in[4];       // int32 [256]
    const void* initres = d_in[5];                   // bool [256]
    const float* roW    = (const float*)d_in[6];     // f32 [10,256]
    const float* rob    = (const float*)d_in[7];     // f32 [10]
    float* out = (float*)d_out;                      // f32 [512,10]

    detect_kernel<<<1, 32>>>((const uint32_t*)x);
    center_kernel<<<1, 256>>>(W, primes, innod, initres);
    pack_win_kernel<<<(RNODES * 128 * 32 + 255) / 256, 256>>>(lut); // 128 MB read
    pack_x_kernel<<<1024, 256>>>(x);
    prep_tab6_kernel<<<(SEC_T6 + 255) / 256, 256>>>(W, primes);
    prep2_kernel<<<(TAB12_ROWS * 128 + 255) / 256, 256>>>();
    reservoir_kernel<<<NSAMP, 128>>>(roW, rob, out);
}

// round 16
// speedup vs baseline: 1.0395x; 1.0395x over previous
#include <cuda_runtime.h>
#include <stdint.h>

#define RNODES 256
#define LUT_LEN 262144            // 2^18 entries per node
#define LUT_WORDS 8192            // 2^18 / 32
#define NSTEP 512
#define NSAMP 512
#define NIN 32
#define NOUT 10

// 6-bit half-groups: 43 (last covers k=252..255; k>=256 guarded to zero)
#define NH6 43
#define TAB6_ROWS (NH6 * 64)
// 12-bit groups: 21 full (g=0..20, k=0..251) + one 4-bit tail (k=252..255)
#define NG12 21
#define TAB12_TAIL (NG12 * 4096)        // 86016
#define TAB12_ROWS (TAB12_TAIL + 16)    // 86032 rows x 128 u32-pairs = 44 MB

// Static device scratch (allocation-free rule).
__device__ uint32_t g_lutbits[RNODES * LUT_WORDS];   // 8 MB bit-packed LUT (L2)
__device__ uint32_t g_nchunk[RNODES];                // reachable 1024-value chunks
__device__ uint16_t g_tab6[TAB6_ROWS * RNODES];      // 1.4 MB half tables
__device__ uint32_t g_tab12[TAB12_ROWS * 128];       // 44 MB pair table (L2)
__device__ uint32_t g_xpack[NSAMP * NSTEP];          // per (m,s): 32 input bits
__device__ int      g_inv[RNODES];                   // node -> input slot, or -1
__device__ int      g_init[RNODES];                  // initial state bits
__device__ int      g_mode;                          // bool enc: 0=i32 1=u8 2=f32

__device__ __forceinline__ int read_bool(const void* p, long i, int mode) {
    if (mode == 0) return ((const int*)p)[i] != 0;
    if (mode == 1) return ((const unsigned char*)p)[i] != 0;
    return ((const float*)p)[i] != 0.0f;
}

__global__ void detect_kernel(const uint32_t* __restrict__ xw) {
    int lane = threadIdx.x;
    if (blockIdx.x || lane >= 32) return;
    int isf = 0, big = 0;
    for (int i = 0; i < 32; i++) {
        uint32_t v = xw[i * 32 + lane];
        if (v == 0x3f800000u) isf = 1;
        if (v > 1u) big = 1;
    }
    unsigned af = __ballot_sync(0xffffffffu, isf);
    unsigned ab = __ballot_sync(0xffffffffu, big);
    if (lane == 0) g_mode = af ? 2 : (ab ? 1 : 0);
}

// Per-node reachable bound: idx <= rowsum_t, so only ceil((rowsum+1)/1024)
// chunks of 1024 LUT values can ever be gathered. One thread per node.
__global__ void bound_kernel(const void* __restrict__ W,
                             const int* __restrict__ primes) {
    int t = threadIdx.x;
    if (blockIdx.x || t >= RNODES) return;
    int mode = g_mode;
    long row = (long)t * RNODES;
    uint32_t rowsum = 0;
    for (int k = 0; k < RNODES; k++)
        if (read_bool(W, row + k, mode)) rowsum += (uint32_t)primes[k];
    uint32_t nch = (rowsum + 1 + 1023) >> 10;
    if (nch > 256) nch = 256;
    g_nchunk[t] = nch;
}

// Warp-ballot LUT pack, bounded to reachable chunks (~46% of 1 GB read).
// 65536 warps: warp gw -> node gw>>8, chunk gw&255 (32 words = 1024 values).
// Layout and indexing of g_lutbits are IDENTICAL to the full pack; words in
// unreachable chunks stay stale and are provably never addressed.
__global__ void pack_lut_kernel(const int* __restrict__ lut) {
    int gw   = (blockIdx.x * blockDim.x + threadIdx.x) >> 5;
    int lane = threadIdx.x & 31;
    int node = gw >> 8, chunk = gw & 255;
    if ((uint32_t)chunk >= g_nchunk[node]) return;   // warp-uniform early out
    const int* src = lut + (size_t)node * LUT_LEN + chunk * 1024;
    uint32_t mine = 0;
#pragma unroll
    for (int w = 0; w < 32; w++) {
        int v = src[w * 32 + lane];
        unsigned m = __ballot_sync(0xffffffffu, v & 1);
        if (lane == w) mine = m;
    }
    g_lutbits[node * LUT_WORDS + chunk * 32 + lane] = mine;
}

// Warp-ballot x pack: 262144 words / 32 per warp = 8192 warps.
__global__ void pack_x_kernel(const void* __restrict__ x) {
    int gwarp = (blockIdx.x * blockDim.x + threadIdx.x) >> 5;
    int lane  = threadIdx.x & 31;
    int mode  = g_mode;
    long base = (long)gwarp * 1024;
    uint32_t mine = 0;
#pragma unroll
    for (int w = 0; w < 32; w++) {
        int v = read_bool(x, base + w * 32 + lane, mode);
        unsigned m = __ballot_sync(0xffffffffu, v);
        if (lane == w) mine = m;
    }
    g_xpack[gwarp * 32 + lane] = mine;
}

// misc (inv/init) + 6-bit half tables
#define SEC_MISC RNODES
#define SEC_T6   (TAB6_ROWS * RNODES)
__global__ void prep_small_kernel(const int* __restrict__ input_nodes,
                                  const void* __restrict__ init_res,
                                  const void* __restrict__ W,
                                  const int* __restrict__ primes) {
    int i = blockIdx.x * blockDim.x + threadIdx.x;
    int mode = g_mode;
    if (i < SEC_MISC) {
        int inv = -1;
#pragma unroll
        for (int q = 0; q < NIN; q++)
            if (input_nodes[q] == i) inv = q;
        g_inv[i] = inv;
        g_init[i] = read_bool(init_res, i, mode);
    }
    i -= SEC_MISC;
    if (i < 0 || i >= SEC_T6) return;
    // tab6 entry (h, c, node): sum over combo bits j of half-group h (k=6h+j)
    int node = i & 255;
    int c    = (i >> 8) & 63;
    int h    = i >> 14;
    uint32_t sum = 0;
#pragma unroll
    for (int j = 0; j < 6; j++) {
        int k = 6 * h + j;
        if ((c & (1 << j)) && k < RNODES) {
            if (read_bool(W, (long)node * RNODES + k, mode))
                sum += (uint32_t)primes[k];
        }
    }
    g_tab6[i] = (uint16_t)sum;
}

// Build paired 12-bit table from 6-bit halves (write-bound, 44 MB).
// Entry (row, t): u16 pair {node t, node t+128}.
__global__ void prep2_kernel() {
    int i = blockIdx.x * blockDim.x + threadIdx.x;
    if (i >= TAB12_ROWS * 128) return;
    int t   = i & 127;
    int row = i >> 7;
    uint32_t lo, hi;
    if (row < TAB12_TAIL) {
        int g  = row >> 12;
        int c  = row & 4095;
        int r0 = (2 * g) * 64 + (c & 63);
        int r1 = (2 * g + 1) * 64 + (c >> 6);
        lo = (uint32_t)g_tab6[r0 * RNODES + t]
           + (uint32_t)g_tab6[r1 * RNODES + t];
        hi = (uint32_t)g_tab6[r0 * RNODES + t + 128]
           + (uint32_t)g_tab6[r1 * RNODES + t + 128];
    } else {
        int r = 42 * 64 + (row - TAB12_TAIL);     // k = 252..255
        lo = g_tab6[r * RNODES + t];
        hi = g_tab6[r * RNODES + t + 128];
    }
    g_tab12[i] = lo | (hi << 16);
}

// 512 CTAs x 128 threads. CTA = one sample; thread t owns nodes t and t+128
// (packed u16 accumulation, spilled every 3 groups). VERBATIM R8 hot kernel.
__global__ void __launch_bounds__(128, 4)
reservoir_kernel(const float* __restrict__ roW,
                 const float* __restrict__ rob,
                 float* __restrict__ out) {
    __shared__ uint32_t sh_xw[NSTEP];
    __shared__ uint32_t sh_r[16];       // 2 bufs * 8 mask words
    __shared__ float    sh_bits[RNODES];

    const int t    = threadIdx.x;       // 0..127
    const int w    = t >> 5;
    const int lane = t & 31;
    const int sid  = blockIdx.x;

    for (int i = t; i < NSTEP; i += 128)
        sh_xw[i] = g_xpack[sid * NSTEP + i];

    const int inv0 = g_inv[t];
    const int inv1 = g_inv[t + 128];
    unsigned b0 = (unsigned)g_init[t];
    unsigned b1 = (unsigned)g_init[t + 128];

    __syncthreads();

    for (int s = 0; s < NSTEP; s++) {
        // 1) input override (before the matvec, as in the reference)
        uint32_t xw = sh_xw[s];
        unsigned a0 = (inv0 >= 0) ? ((xw >> inv0) & 1u) : b0;
        unsigned a1 = (inv1 >= 0) ? ((xw >> inv1) & 1u) : b1;

        // 2) state bitmask words: warp w -> words w and w+4
        unsigned m0 = __ballot_sync(0xffffffffu, a0);
        unsigned m1 = __ballot_sync(0xffffffffu, a1);
        uint32_t* rb = sh_r + (s & 1) * 8;
        if (lane == 0) { rb[w] = m0; rb[w + 4] = m1; }
        __syncthreads();

        uint4 ra  = *(const uint4*)(rb);
        uint4 rb4 = *(const uint4*)(rb + 4);
        uint32_t wv[8] = {ra.x, ra.y, ra.z, ra.w, rb4.x, rb4.y, rb4.z, rb4.w};

        // 3) 12-bit-group pair sums: 22 independent coalesced LDG.32
        uint32_t i0 = 0, i1 = 0;
#pragma unroll
        for (int trip = 0; trip < 7; trip++) {
            uint32_t acc = 0;   // packed u16; 3 groups max < 58.3K
#pragma unroll
            for (int j = 0; j < 3; j++) {
                int g  = trip * 3 + j;
                int bp = 12 * g;
                int wi = bp >> 5, sh = bp & 31;
                uint32_t c = __funnelshift_r(wv[wi], wv[(wi + 1) & 7], sh) & 0xFFFu;
                acc = __vadd2(acc, g_tab12[((uint32_t)g << 19) + (c << 7) + t]);
            }
            i0 += acc & 0xFFFFu;
            i1 += acc >> 16;
        }
        {   // tail 4-bit group (nodes k=252..255)
            uint32_t c = wv[7] >> 28;
            uint32_t e = g_tab12[((uint32_t)TAB12_TAIL << 7) + (c << 7) + t];
            i0 += e & 0xFFFFu;
            i1 += e >> 16;
        }

        // 4) bit-packed LUT gather (8 MB, L2-resident)
        uint32_t w0 = g_lutbits[((uint32_t)t << 13)         + (i0 >> 5)];
        uint32_t w1 = g_lutbits[((uint32_t)(t + 128) << 13) + (i1 >> 5)];
        b0 = (w0 >> (i0 & 31u)) & 1u;
        b1 = (w1 >> (i1 & 31u)) & 1u;
    }

    // Readout: out[m, o] = sum_j rf[m,j] * roW[o,j] + rob[o]
    sh_bits[t]       = (float)b0;
    sh_bits[t + 128] = (float)b1;
    __syncthreads();

    if (t < NOUT) {
        float acc = rob[t];
        const float* wrow = roW + t * RNODES;
#pragma unroll 8
        for (int j = 0; j < RNODES; j++)
            acc += sh_bits[j] * wrow[j];
        out[sid * NOUT + t] = acc;
    }
}

extern "C" void kernel_launch(void* const* d_in, const int* in_sizes, int n_in,
                              void* d_out, int out_size) {
    const void* x       = d_in[0];                   // bool [512,512,4,8] (dtype-detected)
    const int*  innod   = (const int*)d_in[1];       // int32 [32]
    const int*  lut     = (const int*)d_in[2];       // int32 [256, 262144]
    const void* W       = d_in[3];                   // bool [256,256]
    const int*  primes  = (const int*)d_in[4];       // int32 [256]
    const void* initres = d_in[5];                   // bool [256]
    const float* roW    = (const float*)d_in[6];     // f32 [10,256]
    const float* rob    = (const float*)d_in[7];     // f32 [10]
    float* out = (float*)d_out;                      // f32 [512,10]

    detect_kernel<<<1, 32>>>((const uint32_t*)x);
    bound_kernel<<<1, 256>>>(W, primes);
    pack_lut_kernel<<<8192, 256>>>(lut);             // ~0.46 GB effective read
    pack_x_kernel<<<1024, 256>>>(x);
    prep_small_kernel<<<(SEC_MISC + SEC_T6 + 255) / 256, 256>>>(innod, initres, W, primes);
    prep2_kernel<<<(TAB12_ROWS * 128 + 255) / 256, 256>>>();
    reservoir_kernel<<<NSAMP, 128>>>(roW, rob, out);
}